// round 3
// baseline (speedup 1.0000x reference)
#include <cuda_runtime.h>
#include <cuda_bf16.h>

#define N_NODES 100000
#define N_EDGES 3200000

// Padded positions: one aligned 16B gather per endpoint.
__device__ float4 g_pos4[N_NODES];

// Fused + vectorized: pad 4 nodes/thread into g_pos4 and zero the accumulator.
__global__ void __launch_bounds__(256)
prep_kernel(const float4* __restrict__ pos4, float4* __restrict__ out4, int n) {
    const float4 zero = make_float4(0.f, 0.f, 0.f, 0.f);
    int t = blockIdx.x * blockDim.x + threadIdx.x;
    int nq = n >> 2;                       // full groups of 4 nodes
    if (t < nq) {
        float4 a = __ldg(&pos4[3 * t]);
        float4 b = __ldg(&pos4[3 * t + 1]);
        float4 c = __ldg(&pos4[3 * t + 2]);
        int i = 4 * t;
        g_pos4[i]     = make_float4(a.x, a.y, a.z, 0.f);
        g_pos4[i + 1] = make_float4(a.w, b.x, b.y, 0.f);
        g_pos4[i + 2] = make_float4(b.z, b.w, c.x, 0.f);
        g_pos4[i + 3] = make_float4(c.y, c.z, c.w, 0.f);
        out4[i] = zero; out4[i + 1] = zero; out4[i + 2] = zero; out4[i + 3] = zero;
    }
    // tail (n % 4 nodes) handled by thread 0 of block 0
    if (t == 0) {
        const float* p = (const float*)pos4;
        for (int i = nq * 4; i < n; i++) {
            g_pos4[i] = make_float4(p[3 * i], p[3 * i + 1], p[3 * i + 2], 0.f);
            out4[i] = zero;
        }
    }
    cudaTriggerProgrammaticLaunchCompletion();
}

__device__ __forceinline__ void process_edge(int s, int d, float4* out4) {
    float4 ps = __ldg(&g_pos4[s]);
    float4 pd = __ldg(&g_pos4[d]);
    float rx = pd.x - ps.x;
    float ry = pd.y - ps.y;
    float rz = pd.z - ps.z;
    float dot = fmaf(rx, rx, fmaf(ry, ry, rz * rz));
    // rel==0 -> dot==0 -> inv finite, 0*finite = 0 (matches reference)
    float inv = rsqrtf(fmaxf(dot, 1e-24f));
    float x = rx * inv;
    float y = ry * inv;
    float z = rz * inv;
    float* addr = reinterpret_cast<float*>(out4 + d);
    asm volatile("red.global.add.v4.f32 [%0], {%1, %2, %3, %4};"
                 :: "l"(addr), "f"(1.0f), "f"(x), "f"(y), "f"(z)
                 : "memory");
}

// 4 edges/thread. PDL: index streams load while prep is still running;
// gathers wait on grid dependency.
__global__ void __launch_bounds__(256)
edge_kernel(const int4* __restrict__ src4,
            const int4* __restrict__ dst4,
            float4* __restrict__ out4, int n_quads) {
    int t = blockIdx.x * blockDim.x + threadIdx.x;
    int4 s, d;
    bool active = (t < n_quads);
    if (active) {
        s = __ldg(src4 + t);               // independent of prep
        d = __ldg(dst4 + t);
    }
    cudaGridDependencySynchronize();       // wait for g_pos4 + zeroed out4
    if (active) {
        process_edge(s.x, d.x, out4);
        process_edge(s.y, d.y, out4);
        process_edge(s.z, d.z, out4);
        process_edge(s.w, d.w, out4);
    }
    cudaTriggerProgrammaticLaunchCompletion();
}

// 2 nodes/thread; preload independent inputs before the dependency sync.
__global__ void __launch_bounds__(256)
finalize_kernel(const float* __restrict__ node_feat,
                const float* __restrict__ w0,
                const float* __restrict__ w1,
                float4* __restrict__ out4, int n) {
    int i0 = (blockIdx.x * blockDim.x + threadIdx.x) * 2;
    bool act0 = (i0 < n);
    int i1 = i0 + 1;
    bool act1 = (i1 < n);

    float f0 = act0 ? __ldg(&node_feat[i0]) : 0.0f;   // independent of edge kernel
    float f1 = act1 ? __ldg(&node_feat[i1]) : 0.0f;
    float w0v = __ldg(&w0[0]);
    float w1x = __ldg(&w1[0]);
    float w1y = __ldg(&w1[1]);
    float w1z = __ldg(&w1[2]);

    cudaGridDependencySynchronize();       // wait for all red.v4 accumulations

    if (act0) {
        float4 a = out4[i0];
        float cnt = a.x;
        float fr = f0 / fmaxf(cnt, 1.0f);
        out4[i0] = make_float4(w0v * fr * cnt, w1x * fr * a.y,
                               w1y * fr * a.z, w1z * fr * a.w);
    }
    if (act1) {
        float4 a = out4[i1];
        float cnt = a.x;
        float fr = f1 / fmaxf(cnt, 1.0f);
        out4[i1] = make_float4(w0v * fr * cnt, w1x * fr * a.y,
                               w1y * fr * a.z, w1z * fr * a.w);
    }
}

extern "C" void kernel_launch(void* const* d_in, const int* in_sizes, int n_in,
                              void* d_out, int out_size) {
    const float* positions = (const float*)d_in[0];   // [N,3]
    const float* node_feat = (const float*)d_in[1];   // [N,1]
    const float* w0        = (const float*)d_in[2];   // [1]
    const float* w1        = (const float*)d_in[3];   // [3]
    const int*   edge_src  = (const int*)d_in[4];     // [E]
    const int*   edge_dst  = (const int*)d_in[5];     // [E]

    const int n_nodes = in_sizes[1];
    const int n_edges = in_sizes[4];

    float4* out4 = (float4*)d_out;
    const int B = 256;

    // prep: 4 nodes/thread
    int nq_nodes = n_nodes >> 2;
    int prep_blocks = (nq_nodes + B - 1) / B;
    if (prep_blocks == 0) prep_blocks = 1;
    prep_kernel<<<prep_blocks, B>>>((const float4*)positions, out4, n_nodes);

    // PDL attribute shared by dependent launches
    cudaLaunchAttribute attr[1];
    attr[0].id = cudaLaunchAttributeProgrammaticStreamSerialization;
    attr[0].val.programmaticStreamSerializationAllowed = 1;

    int n_quads = n_edges / 4;
    {
        cudaLaunchConfig_t cfg = {};
        cfg.gridDim = dim3((n_quads + B - 1) / B);
        cfg.blockDim = dim3(B);
        cfg.stream = 0;
        cfg.attrs = attr;
        cfg.numAttrs = 1;
        cudaLaunchKernelEx(&cfg, edge_kernel,
                           (const int4*)edge_src, (const int4*)edge_dst,
                           out4, n_quads);
    }

    {
        int n_pairs = (n_nodes + 1) / 2;
        cudaLaunchConfig_t cfg = {};
        cfg.gridDim = dim3((n_pairs + B - 1) / B);
        cfg.blockDim = dim3(B);
        cfg.stream = 0;
        cfg.attrs = attr;
        cfg.numAttrs = 1;
        cudaLaunchKernelEx(&cfg, finalize_kernel,
                           node_feat, w0, w1, out4, n_nodes);
    }
}